// round 12
// baseline (speedup 1.0000x reference)
#include <cuda_runtime.h>
#include <math.h>
#include <stdint.h>
#include <float.h>

#define BT    256   // phase-A threads per block
#define SPLIT 8     // segments per row
#define PB_BT 128   // phase-B threads per block

// Scratch (allocation-free rule: __device__ globals).
__device__ float2       g_part[65536 * SPLIT];  // (mL, s) per (row, seg)
__device__ float        g_bsum[1024];           // phase-B per-block partial sums
__device__ unsigned int g_done = 0;

__device__ __forceinline__ float max4(float4 a) {
    return fmaxf(fmaxf(a.x, a.y), fmaxf(a.z, a.w));
}

// ---------------- Phase A: per-(row,segment) online logsumexp ----------------
__global__ void __launch_bounds__(BT) sce_seg_kernel(
    const float* __restrict__ x, int V, int chunk)
{
    const int row = blockIdx.x >> 3;          // / SPLIT
    const int seg = blockIdx.x & (SPLIT - 1);
    const int tid = threadIdx.x;
    const float L2E = 1.4426950408889634f;    // log2(e)

    const int start = seg * chunk;
    int len = V - start;
    if (len > chunk) len = chunk;
    if (len < 0)     len = 0;
    const float* __restrict__ p = x + (size_t)row * (size_t)V + start;

    float mL = -FLT_MAX;                      // running max, log2 domain
    float s0 = 0.f, s1 = 0.f, s2 = 0.f, s3 = 0.f;

    // Peel to 16B alignment.
    int align = (int)(((uintptr_t)p) & 15);
    int peel  = ((16 - align) & 15) >> 2;     // 0..3 floats
    if (peel > len) peel = len;
    if (tid < peel) { mL = p[tid] * L2E; s0 = 1.0f; }

    // Main stream: 4x float4 per iteration, front-batched loads.
    const float4* __restrict__ rv = (const float4*)(p + peel);
    const int nv = (len - peel) >> 2;
    int i = tid;
    for (; i + 3 * BT < nv; i += 4 * BT) {
        float4 a = __ldcs(&rv[i]);
        float4 b = __ldcs(&rv[i +     BT]);
        float4 c4 = __ldcs(&rv[i + 2 * BT]);
        float4 d = __ldcs(&rv[i + 3 * BT]);
        float cL = fmaxf(fmaxf(max4(a), max4(b)), fmaxf(max4(c4), max4(d))) * L2E;
        if (cL > mL) {
            float f = exp2f(mL - cL);
            s0 *= f; s1 *= f; s2 *= f; s3 *= f;
            mL = cL;
        }
        s0 += exp2f(fmaf(a.x, L2E, -mL));
        s1 += exp2f(fmaf(a.y, L2E, -mL));
        s2 += exp2f(fmaf(a.z, L2E, -mL));
        s3 += exp2f(fmaf(a.w, L2E, -mL));
        s0 += exp2f(fmaf(b.x, L2E, -mL));
        s1 += exp2f(fmaf(b.y, L2E, -mL));
        s2 += exp2f(fmaf(b.z, L2E, -mL));
        s3 += exp2f(fmaf(b.w, L2E, -mL));
        s0 += exp2f(fmaf(c4.x, L2E, -mL));
        s1 += exp2f(fmaf(c4.y, L2E, -mL));
        s2 += exp2f(fmaf(c4.z, L2E, -mL));
        s3 += exp2f(fmaf(c4.w, L2E, -mL));
        s0 += exp2f(fmaf(d.x, L2E, -mL));
        s1 += exp2f(fmaf(d.y, L2E, -mL));
        s2 += exp2f(fmaf(d.z, L2E, -mL));
        s3 += exp2f(fmaf(d.w, L2E, -mL));
    }
    for (; i < nv; i += BT) {
        float4 a = __ldcs(&rv[i]);
        float cL = max4(a) * L2E;
        if (cL > mL) {
            float f = exp2f(mL - cL);
            s0 *= f; s1 *= f; s2 *= f; s3 *= f;
            mL = cL;
        }
        s0 += exp2f(fmaf(a.x, L2E, -mL));
        s1 += exp2f(fmaf(a.y, L2E, -mL));
        s2 += exp2f(fmaf(a.z, L2E, -mL));
        s3 += exp2f(fmaf(a.w, L2E, -mL));
    }
    for (int j = peel + 4 * nv + tid; j < len; j += BT) {
        float xv = p[j];
        float cL = xv * L2E;
        if (cL > mL) {
            float f = exp2f(mL - cL);
            s0 *= f; s1 *= f; s2 *= f; s3 *= f;
            mL = cL;
        }
        s0 += exp2f(fmaf(xv, L2E, -mL));
    }

    float s = (s0 + s1) + (s2 + s3);

    // Warp-level (mL, s) merge (log2 domain).
    #pragma unroll
    for (int off = 16; off > 0; off >>= 1) {
        float m2 = __shfl_xor_sync(0xffffffffu, mL, off);
        float sx = __shfl_xor_sync(0xffffffffu, s, off);
        float nm = fmaxf(mL, m2);
        s = s * exp2f(mL - nm) + sx * exp2f(m2 - nm);
        mL = nm;
    }

    __shared__ float smx[BT / 32];
    __shared__ float ssx[BT / 32];
    const int warp = tid >> 5;
    const int lane = tid & 31;
    if (lane == 0) { smx[warp] = mL; ssx[warp] = s; }
    __syncthreads();

    if (warp == 0) {
        mL = (lane < BT / 32) ? smx[lane] : -FLT_MAX;
        s  = (lane < BT / 32) ? ssx[lane] : 0.0f;
        #pragma unroll
        for (int off = (BT / 32) / 2; off > 0; off >>= 1) {
            float m2 = __shfl_xor_sync(0xffffffffu, mL, off);
            float sx = __shfl_xor_sync(0xffffffffu, s, off);
            float nm = fmaxf(mL, m2);
            s = s * exp2f(mL - nm) + sx * exp2f(m2 - nm);
            mL = nm;
        }
        if (lane == 0)
            g_part[blockIdx.x] = make_float2(mL, s);
    }
}

// ------- Phase B: merge segments, gather target logit, global mean ----------
__global__ void __launch_bounds__(PB_BT) sce_merge_kernel(
    const float* __restrict__ x,
    const int*   __restrict__ tgt,
    int N, int V, float log_scale,
    float* __restrict__ out)
{
    const int tid = threadIdx.x;
    const int row = blockIdx.x * PB_BT + tid;
    const float LN2 = 0.6931471805599453f;

    float loss = 0.0f;
    if (row < N) {
        float mL = -FLT_MAX, s = 0.0f;
        #pragma unroll
        for (int k = 0; k < SPLIT; k++) {
            float2 pp = g_part[row * SPLIT + k];
            float nm = fmaxf(mL, pp.x);
            s = s * exp2f(mL - nm) + pp.y * exp2f(pp.x - nm);
            mL = nm;
        }
        float xt = __ldg(&x[(size_t)row * (size_t)V + tgt[row]]);
        loss = fmaf(mL, LN2, logf(s)) - xt - log_scale;
    }

    // Block reduce.
    #pragma unroll
    for (int off = 16; off > 0; off >>= 1)
        loss += __shfl_xor_sync(0xffffffffu, loss, off);

    __shared__ float w[PB_BT / 32];
    __shared__ int   s_last;
    const int warp = tid >> 5;
    const int lane = tid & 31;
    if (lane == 0) w[warp] = loss;
    __syncthreads();
    if (tid == 0) {
        float bs = 0.0f;
        #pragma unroll
        for (int k = 0; k < PB_BT / 32; k++) bs += w[k];
        g_bsum[blockIdx.x] = bs;
        __threadfence();
        unsigned int v = atomicAdd(&g_done, 1u);
        s_last = (v == gridDim.x - 1) ? 1 : 0;
    }
    __syncthreads();

    // Last block computes the deterministic final mean.
    if (s_last) {
        __threadfence();
        float acc = 0.0f;
        for (int k = tid; k < (int)gridDim.x; k += PB_BT)
            acc += g_bsum[k];
        #pragma unroll
        for (int off = 16; off > 0; off >>= 1)
            acc += __shfl_xor_sync(0xffffffffu, acc, off);
        if (lane == 0) w[warp] = acc;
        __syncthreads();
        if (tid == 0) {
            float t = 0.0f;
            #pragma unroll
            for (int k = 0; k < PB_BT / 32; k++) t += w[k];
            out[0] = t / (float)N;
            g_done = 0;   // reset for next graph replay
        }
    }
}

extern "C" void kernel_launch(void* const* d_in, const int* in_sizes, int n_in,
                              void* d_out, int out_size)
{
    const float* x   = (const float*)d_in[0];
    const int*   tgt = (const int*)d_in[1];
    float*       out = (float*)d_out;

    const int N = in_sizes[1];              // 4096 rows
    const int V = in_sizes[0] / N;          // 50257 classes

    const float ALPHA = 0.154f;
    const float scale = 1.0f - ALPHA + ALPHA / (float)V;
    const float log_scale = logf(scale);
    const int chunk = (V + SPLIT - 1) / SPLIT;

    sce_seg_kernel<<<N * SPLIT, BT>>>(x, V, chunk);
    const int pbg = (N + PB_BT - 1) / PB_BT;
    sce_merge_kernel<<<pbg, PB_BT>>>(x, tgt, N, V, log_scale, out);
}

// round 13
// speedup vs baseline: 1.3035x; 1.3035x over previous
#include <cuda_runtime.h>
#include <math.h>
#include <stdint.h>
#include <float.h>

#define BT    256   // threads per block
#define SPLIT 2     // segments per row

// Scratch (allocation-free rule: __device__ globals).
__device__ float2       g_part[65536 * SPLIT];   // (mL, s) per (row, seg)
__device__ float        g_row_loss[65536];
__device__ unsigned int g_rowcnt[65536];         // zero-init; reset after use
__device__ unsigned int g_done = 0;

__device__ __forceinline__ float max4(float4 a) {
    return fmaxf(fmaxf(a.x, a.y), fmaxf(a.z, a.w));
}

__global__ void __launch_bounds__(BT) sce_kernel(
    const float* __restrict__ x,
    const int*   __restrict__ tgt,
    int N, int V, int chunk, float log_scale,
    float* __restrict__ out)
{
    const int row = blockIdx.x >> 1;
    const int seg = blockIdx.x & 1;
    const int tid = threadIdx.x;
    const float L2E = 1.4426950408889634f;   // log2(e)
    const float LN2 = 0.6931471805599453f;

    const int start = seg * chunk;
    int len = V - start;
    if (len > chunk) len = chunk;
    const float* __restrict__ p = x + (size_t)row * (size_t)V + start;

    float mL = -FLT_MAX;                      // running max in log2 domain
    float s0 = 0.f, s1 = 0.f, s2 = 0.f, s3 = 0.f;

    // ---- Peel to 16B alignment. ----
    int align = (int)(((uintptr_t)p) & 15);
    int peel  = ((16 - align) & 15) >> 2;     // 0..3 floats
    if (peel > len) peel = len;
    if (tid < peel) { mL = p[tid] * L2E; s0 = 1.0f; }

    // ---- Main stream: 4x float4 per iteration, front-batched loads. ----
    const float4* __restrict__ rv = (const float4*)(p + peel);
    const int nv = (len - peel) >> 2;
    int i = tid;
    for (; i + 3 * BT < nv; i += 4 * BT) {
        float4 a  = __ldcs(&rv[i]);
        float4 b  = __ldcs(&rv[i +     BT]);
        float4 c4 = __ldcs(&rv[i + 2 * BT]);
        float4 d  = __ldcs(&rv[i + 3 * BT]);
        float cL = fmaxf(fmaxf(max4(a), max4(b)), fmaxf(max4(c4), max4(d))) * L2E;
        if (cL > mL) {
            float f = exp2f(mL - cL);
            s0 *= f; s1 *= f; s2 *= f; s3 *= f;
            mL = cL;
        }
        s0 += exp2f(fmaf(a.x, L2E, -mL));
        s1 += exp2f(fmaf(a.y, L2E, -mL));
        s2 += exp2f(fmaf(a.z, L2E, -mL));
        s3 += exp2f(fmaf(a.w, L2E, -mL));
        s0 += exp2f(fmaf(b.x, L2E, -mL));
        s1 += exp2f(fmaf(b.y, L2E, -mL));
        s2 += exp2f(fmaf(b.z, L2E, -mL));
        s3 += exp2f(fmaf(b.w, L2E, -mL));
        s0 += exp2f(fmaf(c4.x, L2E, -mL));
        s1 += exp2f(fmaf(c4.y, L2E, -mL));
        s2 += exp2f(fmaf(c4.z, L2E, -mL));
        s3 += exp2f(fmaf(c4.w, L2E, -mL));
        s0 += exp2f(fmaf(d.x, L2E, -mL));
        s1 += exp2f(fmaf(d.y, L2E, -mL));
        s2 += exp2f(fmaf(d.z, L2E, -mL));
        s3 += exp2f(fmaf(d.w, L2E, -mL));
    }
    for (; i < nv; i += BT) {
        float4 a = __ldcs(&rv[i]);
        float cL = max4(a) * L2E;
        if (cL > mL) {
            float f = exp2f(mL - cL);
            s0 *= f; s1 *= f; s2 *= f; s3 *= f;
            mL = cL;
        }
        s0 += exp2f(fmaf(a.x, L2E, -mL));
        s1 += exp2f(fmaf(a.y, L2E, -mL));
        s2 += exp2f(fmaf(a.z, L2E, -mL));
        s3 += exp2f(fmaf(a.w, L2E, -mL));
    }
    for (int j = peel + 4 * nv + tid; j < len; j += BT) {
        float xv = p[j];
        float cL = xv * L2E;
        if (cL > mL) {
            float f = exp2f(mL - cL);
            s0 *= f; s1 *= f; s2 *= f; s3 *= f;
            mL = cL;
        }
        s0 += exp2f(fmaf(xv, L2E, -mL));
    }

    float s = (s0 + s1) + (s2 + s3);

    // ---- Warp-level (mL, s) merge (log2 domain). ----
    #pragma unroll
    for (int off = 16; off > 0; off >>= 1) {
        float m2 = __shfl_xor_sync(0xffffffffu, mL, off);
        float sx = __shfl_xor_sync(0xffffffffu, s, off);
        float nm = fmaxf(mL, m2);
        s = s * exp2f(mL - nm) + sx * exp2f(m2 - nm);
        mL = nm;
    }

    __shared__ float smx[BT / 32];
    __shared__ float ssx[BT / 32];
    __shared__ int   s_role;
    const int warp = tid >> 5;
    const int lane = tid & 31;
    if (lane == 0) { smx[warp] = mL; ssx[warp] = s; }
    __syncthreads();

    if (warp == 0) {
        mL = (lane < BT / 32) ? smx[lane] : -FLT_MAX;
        s  = (lane < BT / 32) ? ssx[lane] : 0.0f;
        #pragma unroll
        for (int off = (BT / 32) / 2; off > 0; off >>= 1) {
            float m2 = __shfl_xor_sync(0xffffffffu, mL, off);
            float sx = __shfl_xor_sync(0xffffffffu, s, off);
            float nm = fmaxf(mL, m2);
            s = s * exp2f(mL - nm) + sx * exp2f(m2 - nm);
            mL = nm;
        }
        if (lane == 0) {
            int do_global = 0;
            g_part[blockIdx.x] = make_float2(mL, s);
            __threadfence();
            unsigned int v = atomicAdd(&g_rowcnt[row], 1u);
            if (v == SPLIT - 1) {
                // Second block of this row: merge in fixed index order.
                __threadfence();
                float rm = -FLT_MAX, rs = 0.0f;
                #pragma unroll
                for (int k = 0; k < SPLIT; k++) {
                    float2 pp = g_part[row * SPLIT + k];
                    float nm = fmaxf(rm, pp.x);
                    rs = rs * exp2f(rm - nm) + pp.y * exp2f(pp.x - nm);
                    rm = nm;
                }
                float xt = __ldg(&x[(size_t)row * (size_t)V + tgt[row]]);
                g_row_loss[row] = fmaf(rm, LN2, logf(rs)) - xt - log_scale;
                g_rowcnt[row] = 0;           // reset for next graph replay
                __threadfence();
                unsigned int w = atomicAdd(&g_done, 1u);
                do_global = (w == (unsigned int)(N - 1)) ? 1 : 0;
            }
            s_role = do_global;
        }
    }
    __syncthreads();

    // ---- Last row-merger block computes the deterministic global mean. ----
    if (s_role) {
        __threadfence();   // acquire all rows' losses
        float acc = 0.0f;
        for (int j = tid; j < N; j += BT)
            acc += g_row_loss[j];

        #pragma unroll
        for (int off = 16; off > 0; off >>= 1)
            acc += __shfl_xor_sync(0xffffffffu, acc, off);

        __shared__ float w2[BT / 32];
        if (lane == 0) w2[warp] = acc;
        __syncthreads();
        if (warp == 0) {
            acc = (lane < BT / 32) ? w2[lane] : 0.0f;
            #pragma unroll
            for (int off = (BT / 32) / 2; off > 0; off >>= 1)
                acc += __shfl_xor_sync(0xffffffffu, acc, off);
            if (lane == 0) {
                out[0] = acc / (float)N;
                g_done = 0;   // reset for next graph replay
            }
        }
    }
}

extern "C" void kernel_launch(void* const* d_in, const int* in_sizes, int n_in,
                              void* d_out, int out_size)
{
    const float* x   = (const float*)d_in[0];
    const int*   tgt = (const int*)d_in[1];
    float*       out = (float*)d_out;

    const int N = in_sizes[1];              // 4096 rows
    const int V = in_sizes[0] / N;          // 50257 classes

    const float ALPHA = 0.154f;
    const float scale = 1.0f - ALPHA + ALPHA / (float)V;
    const float log_scale = logf(scale);
    const int chunk = (V + SPLIT - 1) / SPLIT;

    sce_kernel<<<N * SPLIT, BT>>>(x, tgt, N, V, chunk, log_scale, out);
}